// round 11
// baseline (speedup 1.0000x reference)
#include <cuda_runtime.h>
#include <stdint.h>

#define N_NODES 50000
#define N_EDGES 800000
#define D 64
#define N_LAYERS 12

typedef unsigned long long u64;

__device__ float g_aggr[N_NODES * D];
__device__ float g_buf0[N_NODES * D];
__device__ float g_buf1[N_NODES * D];
// CSR-sorted edge arrays (built once per launch)
__device__ int   g_deg[N_NODES];
__device__ int   g_cur[N_NODES];
__device__ int   g_sd[N_EDGES];    // packed: src | (dst << 16)
__device__ float g_w[N_EDGES];

// ---------------------------------------------------------------------------
// CSR build: histogram -> scan -> permute (sort edges by dst, pack src|dst)
// ---------------------------------------------------------------------------
__global__ void hist_kernel(const int* __restrict__ ei) {
    int e = blockIdx.x * blockDim.x + threadIdx.x;
    if (e < N_EDGES) atomicAdd(&g_deg[ei[N_EDGES + e]], 1);
}

#define SCAN_T 1024
#define SCAN_C 49
__global__ void scan_kernel() {
    __shared__ int part[SCAN_T];
    int t = threadIdx.x;
    int base = t * SCAN_C;
    int s = 0;
    for (int j = 0; j < SCAN_C; ++j) {
        int idx = base + j;
        if (idx < N_NODES) s += g_deg[idx];
    }
    part[t] = s;
    __syncthreads();
    for (int off = 1; off < SCAN_T; off <<= 1) {
        int v = (t >= off) ? part[t - off] : 0;
        __syncthreads();
        part[t] += v;
        __syncthreads();
    }
    int run = (t > 0) ? part[t - 1] : 0;
    for (int j = 0; j < SCAN_C; ++j) {
        int idx = base + j;
        if (idx < N_NODES) {
            g_cur[idx] = run;
            run += g_deg[idx];
        }
    }
}

__global__ void permute_kernel(const int* __restrict__ ei,
                               const float* __restrict__ ew) {
    int e = blockIdx.x * blockDim.x + threadIdx.x;
    if (e >= N_EDGES) return;
    int d = ei[N_EDGES + e];
    int pos = atomicAdd(&g_cur[d], 1);
    g_sd[pos] = ei[e] | (d << 16);
    g_w[pos] = ew[e];
}

// ---------------------------------------------------------------------------
// Aggregation (R10 winner + reg cap): warp owns 64 dst-sorted edges,
// 8 batches of 8, 2-stage metadata prefetch, register segmented sum,
// red.global flush on dst change. launch_bounds(256,4) caps regs at 64.
// ---------------------------------------------------------------------------
#define AGG_SPAN 64
#define N_SPANS (N_EDGES / AGG_SPAN)   // 12500

__device__ __forceinline__ void flush_v2(float* aggr, int dstn, int lane, float2 a) {
    float* p = aggr + (size_t)dstn * D + 2 * lane;
    u64 gp = (u64)__cvta_generic_to_global(p);
    asm volatile("red.global.add.v2.f32 [%0], {%1,%2};"
                 :: "l"(gp), "f"(a.x), "f"(a.y) : "memory");
}

__global__ void __launch_bounds__(256, 4)
aggregate_kernel(const float* __restrict__ xin, float* __restrict__ aggr) {
    int warp = threadIdx.x >> 5, lane = threadIdx.x & 31;
    int span = blockIdx.x * 8 + warp;
    if (span >= N_SPANS) return;
    int e0 = span * AGG_SPAN;

    const int4* sdp = reinterpret_cast<const int4*>(g_sd + e0);
    const float4* wp = reinterpret_cast<const float4*>(g_w + e0);

    int4 sdA = sdp[0], sdB = sdp[1];
    float4 wA = wp[0], wB = wp[1];

    float2 acc = make_float2(0.f, 0.f);
    int cur = -1;

#pragma unroll
    for (int bt = 0; bt < 8; ++bt) {
        int sd[8] = {sdA.x, sdA.y, sdA.z, sdA.w, sdB.x, sdB.y, sdB.z, sdB.w};
        float wt[8] = {wA.x, wA.y, wA.z, wA.w, wB.x, wB.y, wB.z, wB.w};

        float2 v[8];
#pragma unroll
        for (int j = 0; j < 8; ++j) {
            int src = sd[j] & 0xFFFF;
            v[j] = *reinterpret_cast<const float2*>(xin + (size_t)src * D + 2 * lane);
        }

        if (bt < 7) {
            sdA = sdp[2 * bt + 2];
            sdB = sdp[2 * bt + 3];
            wA = wp[2 * bt + 2];
            wB = wp[2 * bt + 3];
        }

#pragma unroll
        for (int j = 0; j < 8; ++j) {
            int d = ((unsigned)sd[j]) >> 16;
            if (d != cur) {
                if (cur >= 0) flush_v2(aggr, cur, lane, acc);
                acc = make_float2(0.f, 0.f);
                cur = d;
            }
            acc.x += v[j].x * wt[j];
            acc.y += v[j].y * wt[j];
        }
    }
    if (cur >= 0) flush_v2(aggr, cur, lane, acc);
}

// ---------------------------------------------------------------------------
// Update: xout = l2norm( concat(l2norm(aggr), x) @ W + b ), FFMA2 GEMM.
// TB=64, 256 threads, 3 CTA/SM. New thread map: 2 rows x 8 cols per thread
// (tx=tid&7 -> cols tx*8..+7, ty=tid>>3 -> rows ty*2,ty*2+1) -> fewer bcast
// MOVs per FFMA2. Zeroes aggr rows after read.
// ---------------------------------------------------------------------------
#define TB 64
#define HSTR 132
#define N_TILES ((N_NODES + TB - 1) / TB)   // 782
#define SMEM_BYTES ((128 * 64 + TB * HSTR) * 4)

__device__ __forceinline__ u64 fma2(u64 a, u64 b, u64 c) {
    u64 d;
    asm("fma.rn.f32x2 %0, %1, %2, %3;" : "=l"(d) : "l"(a), "l"(b), "l"(c));
    return d;
}
__device__ __forceinline__ u64 bcast2(float x) {
    u64 d;
    asm("mov.b64 %0, {%1, %1};" : "=l"(d) : "f"(x));
    return d;
}
__device__ __forceinline__ u64 pack2(float lo, float hi) {
    u64 d;
    asm("mov.b64 %0, {%1, %2};" : "=l"(d) : "f"(lo), "f"(hi));
    return d;
}
__device__ __forceinline__ float2 unpack2(u64 v) {
    float lo, hi;
    asm("mov.b64 {%0, %1}, %2;" : "=f"(lo), "=f"(hi) : "l"(v));
    return make_float2(lo, hi);
}

__global__ void __launch_bounds__(256, 3)
update_kernel(float* __restrict__ aggr,
              const float* __restrict__ xin,
              const float* __restrict__ W,
              const float* __restrict__ b,
              float* __restrict__ xout) {
    extern __shared__ float smem[];
    float* W_s = smem;             // 128*64
    float* h_s = smem + 128 * 64;  // TB x HSTR

    int tid = threadIdx.x;
    int lane = tid & 31;
    int warp = tid >> 5;

    {
        const float4* Wv = reinterpret_cast<const float4*>(W);
        float4* Wsv = reinterpret_cast<float4*>(W_s);
#pragma unroll
        for (int i = 0; i < 8; ++i)
            Wsv[tid + i * 256] = Wv[tid + i * 256];
    }

    // GEMM map: tx -> 8 cols (tx*8..+7), ty -> 2 rows (ty*2, ty*2+1)
    int tx = tid & 7, ty = tid >> 3;
    u64 bias[4];
#pragma unroll
    for (int c = 0; c < 4; ++c)
        bias[c] = pack2(b[tx * 8 + 2 * c], b[tx * 8 + 2 * c + 1]);

    int p1_node = (warp << 3) + (lane >> 2);
    int p1_p = lane & 3;

    for (int tile = blockIdx.x; tile < N_TILES; tile += gridDim.x) {
        __syncthreads();

        // ---- Phase 1: load aggr + x, l2norm(aggr), fill h_s, zero aggr rows
        {
            int node = tile * TB + p1_node;
            float4 a[4], xv[4];
            if (node < N_NODES) {
                const float4* ar = reinterpret_cast<const float4*>(aggr + (size_t)node * D);
                const float4* xr = reinterpret_cast<const float4*>(xin + (size_t)node * D);
#pragma unroll
                for (int j = 0; j < 4; ++j) {
                    a[j]  = ar[p1_p + j * 4];
                    xv[j] = xr[p1_p + j * 4];
                }
                float4 z = make_float4(0.f, 0.f, 0.f, 0.f);
                float4* aw = reinterpret_cast<float4*>(aggr + (size_t)node * D);
#pragma unroll
                for (int j = 0; j < 4; ++j) aw[p1_p + j * 4] = z;
            } else {
#pragma unroll
                for (int j = 0; j < 4; ++j) {
                    a[j] = make_float4(0.f, 0.f, 0.f, 0.f);
                    xv[j] = a[j];
                }
            }
            float ss = 0.f;
#pragma unroll
            for (int j = 0; j < 4; ++j)
                ss += a[j].x * a[j].x + a[j].y * a[j].y
                    + a[j].z * a[j].z + a[j].w * a[j].w;
            ss += __shfl_xor_sync(0xFFFFFFFFu, ss, 1);
            ss += __shfl_xor_sync(0xFFFFFFFFu, ss, 2);
            float inv = 1.0f / fmaxf(sqrtf(ss), 1e-12f);

            float4* hr = reinterpret_cast<float4*>(h_s + p1_node * HSTR);
#pragma unroll
            for (int j = 0; j < 4; ++j) {
                float4 an;
                an.x = a[j].x * inv; an.y = a[j].y * inv;
                an.z = a[j].z * inv; an.w = a[j].w * inv;
                hr[p1_p + j * 4] = an;
                hr[16 + p1_p + j * 4] = xv[j];
            }
        }
        __syncthreads();

        // ---- Phase 2: GEMM, 2 rows x 8 cols per thread, f32x2 FFMA
        u64 acc2[2][4];
#pragma unroll
        for (int i = 0; i < 2; ++i)
#pragma unroll
            for (int c = 0; c < 4; ++c) acc2[i][c] = bias[c];

        const float* h0p = h_s + (ty * 2) * HSTR;
        const float* h1p = h0p + HSTR;
#pragma unroll 2
        for (int k = 0; k < 128; k += 4) {
            float4 h0 = *reinterpret_cast<const float4*>(h0p + k);
            float4 h1 = *reinterpret_cast<const float4*>(h1p + k);
            float h0a[4] = {h0.x, h0.y, h0.z, h0.w};
            float h1a[4] = {h1.x, h1.y, h1.z, h1.w};
#pragma unroll
            for (int kk = 0; kk < 4; ++kk) {
                const float* wrow = W_s + (k + kk) * 64 + tx * 8;
                ulonglong2 wa = *reinterpret_cast<const ulonglong2*>(wrow);
                ulonglong2 wb = *reinterpret_cast<const ulonglong2*>(wrow + 4);
                u64 ha = bcast2(h0a[kk]);
                acc2[0][0] = fma2(ha, wa.x, acc2[0][0]);
                acc2[0][1] = fma2(ha, wa.y, acc2[0][1]);
                acc2[0][2] = fma2(ha, wb.x, acc2[0][2]);
                acc2[0][3] = fma2(ha, wb.y, acc2[0][3]);
                u64 hb = bcast2(h1a[kk]);
                acc2[1][0] = fma2(hb, wa.x, acc2[1][0]);
                acc2[1][1] = fma2(hb, wa.y, acc2[1][1]);
                acc2[1][2] = fma2(hb, wb.x, acc2[1][2]);
                acc2[1][3] = fma2(hb, wb.y, acc2[1][3]);
            }
        }

        // ---- Phase 3: row l2norm across the 8 tx threads (lane bits 0..2)
#pragma unroll
        for (int i = 0; i < 2; ++i) {
            int r = ty * 2 + i;
            int node = tile * TB + r;
            float2 c0 = unpack2(acc2[i][0]);
            float2 c1 = unpack2(acc2[i][1]);
            float2 c2 = unpack2(acc2[i][2]);
            float2 c3 = unpack2(acc2[i][3]);
            float ss = c0.x * c0.x + c0.y * c0.y + c1.x * c1.x + c1.y * c1.y
                     + c2.x * c2.x + c2.y * c2.y + c3.x * c3.x + c3.y * c3.y;
            ss += __shfl_xor_sync(0xFFFFFFFFu, ss, 1);
            ss += __shfl_xor_sync(0xFFFFFFFFu, ss, 2);
            ss += __shfl_xor_sync(0xFFFFFFFFu, ss, 4);
            float inv = 1.0f / fmaxf(sqrtf(ss), 1e-12f);
            if (node < N_NODES) {
                float4 o0, o1;
                o0.x = c0.x * inv; o0.y = c0.y * inv;
                o0.z = c1.x * inv; o0.w = c1.y * inv;
                o1.x = c2.x * inv; o1.y = c2.y * inv;
                o1.z = c3.x * inv; o1.w = c3.y * inv;
                float* orow = xout + (size_t)node * D + tx * 8;
                *reinterpret_cast<float4*>(orow) = o0;
                *reinterpret_cast<float4*>(orow + 4) = o1;
            }
        }
    }
}

// ---------------------------------------------------------------------------
extern "C" void kernel_launch(void* const* d_in, const int* in_sizes, int n_in,
                              void* d_out, int out_size) {
    const float* x  = (const float*)d_in[0];
    const int* ei   = (const int*)d_in[1];
    const float* ew = (const float*)d_in[2];
    const float* W  = (const float*)d_in[3];
    const float* b  = (const float*)d_in[4];
    float* out      = (float*)d_out;

    float *aggr, *buf0, *buf1;
    int* deg;
    cudaGetSymbolAddress((void**)&aggr, g_aggr);
    cudaGetSymbolAddress((void**)&buf0, g_buf0);
    cudaGetSymbolAddress((void**)&buf1, g_buf1);
    cudaGetSymbolAddress((void**)&deg, g_deg);

    cudaFuncSetAttribute(update_kernel,
                         cudaFuncAttributeMaxDynamicSharedMemorySize,
                         SMEM_BYTES);

    const int edge_blocks = (N_EDGES + 255) / 256;
    const int agg_blocks = (N_SPANS + 7) / 8;   // 1563
    const int upd_blocks = 391;                 // 782 tiles / exactly 2 each

    // CSR build (once per call)
    cudaMemsetAsync(deg, 0, N_NODES * sizeof(int), 0);
    hist_kernel<<<edge_blocks, 256>>>(ei);
    scan_kernel<<<1, SCAN_T>>>();
    permute_kernel<<<edge_blocks, 256>>>(ei, ew);

    // aggr starts zero; update re-zeros it each layer
    cudaMemsetAsync(aggr, 0, (size_t)N_NODES * D * sizeof(float), 0);

    const float* cur = x;
    for (int l = 0; l < N_LAYERS; ++l) {
        aggregate_kernel<<<agg_blocks, 256>>>(cur, aggr);
        float* nxt = (l == N_LAYERS - 1) ? out : ((l & 1) ? buf1 : buf0);
        update_kernel<<<upd_blocks, 256, SMEM_BYTES>>>(
            aggr, cur, W + (size_t)l * 2 * D * D, b + (size_t)l * D, nxt);
        cur = nxt;
    }
}

// round 12
// speedup vs baseline: 1.6244x; 1.6244x over previous
#include <cuda_runtime.h>
#include <stdint.h>

#define N_NODES 50000
#define N_EDGES 800000
#define D 64
#define N_LAYERS 12

typedef unsigned long long u64;

__device__ float g_aggr[N_NODES * D];
__device__ float g_buf0[N_NODES * D];
__device__ float g_buf1[N_NODES * D];
// CSR-sorted edge arrays (built once per launch)
__device__ int   g_deg[N_NODES];
__device__ int   g_cur[N_NODES];
__device__ int   g_sd[N_EDGES];    // packed: src | (dst << 16)
__device__ float g_w[N_EDGES];

// ---------------------------------------------------------------------------
// CSR build: histogram -> scan -> permute (sort edges by dst, pack src|dst)
// ---------------------------------------------------------------------------
__global__ void hist_kernel(const int* __restrict__ ei) {
    int e = blockIdx.x * blockDim.x + threadIdx.x;
    if (e < N_EDGES) atomicAdd(&g_deg[ei[N_EDGES + e]], 1);
}

#define SCAN_T 1024
#define SCAN_C 49
__global__ void scan_kernel() {
    __shared__ int part[SCAN_T];
    int t = threadIdx.x;
    int base = t * SCAN_C;
    int s = 0;
    for (int j = 0; j < SCAN_C; ++j) {
        int idx = base + j;
        if (idx < N_NODES) s += g_deg[idx];
    }
    part[t] = s;
    __syncthreads();
    for (int off = 1; off < SCAN_T; off <<= 1) {
        int v = (t >= off) ? part[t - off] : 0;
        __syncthreads();
        part[t] += v;
        __syncthreads();
    }
    int run = (t > 0) ? part[t - 1] : 0;
    for (int j = 0; j < SCAN_C; ++j) {
        int idx = base + j;
        if (idx < N_NODES) {
            g_cur[idx] = run;
            run += g_deg[idx];
        }
    }
}

__global__ void permute_kernel(const int* __restrict__ ei,
                               const float* __restrict__ ew) {
    int e = blockIdx.x * blockDim.x + threadIdx.x;
    if (e >= N_EDGES) return;
    int d = ei[N_EDGES + e];
    int pos = atomicAdd(&g_cur[d], 1);
    g_sd[pos] = ei[e] | (d << 16);
    g_w[pos] = ew[e];
}

// ---------------------------------------------------------------------------
// Aggregation (R11 winner): warp owns 64 dst-sorted edges, 8 batches of 8,
// 2-stage metadata prefetch, register segmented sum, red.global flush on
// dst change. launch_bounds(256,4) caps regs at 64.
// ---------------------------------------------------------------------------
#define AGG_SPAN 64
#define N_SPANS (N_EDGES / AGG_SPAN)   // 12500

__device__ __forceinline__ void flush_v2(float* aggr, int dstn, int lane, float2 a) {
    float* p = aggr + (size_t)dstn * D + 2 * lane;
    u64 gp = (u64)__cvta_generic_to_global(p);
    asm volatile("red.global.add.v2.f32 [%0], {%1,%2};"
                 :: "l"(gp), "f"(a.x), "f"(a.y) : "memory");
}

__global__ void __launch_bounds__(256, 4)
aggregate_kernel(const float* __restrict__ xin, float* __restrict__ aggr) {
    int warp = threadIdx.x >> 5, lane = threadIdx.x & 31;
    int span = blockIdx.x * 8 + warp;
    if (span >= N_SPANS) return;
    int e0 = span * AGG_SPAN;

    const int4* sdp = reinterpret_cast<const int4*>(g_sd + e0);
    const float4* wp = reinterpret_cast<const float4*>(g_w + e0);

    int4 sdA = sdp[0], sdB = sdp[1];
    float4 wA = wp[0], wB = wp[1];

    float2 acc = make_float2(0.f, 0.f);
    int cur = -1;

#pragma unroll
    for (int bt = 0; bt < 8; ++bt) {
        int sd[8] = {sdA.x, sdA.y, sdA.z, sdA.w, sdB.x, sdB.y, sdB.z, sdB.w};
        float wt[8] = {wA.x, wA.y, wA.z, wA.w, wB.x, wB.y, wB.z, wB.w};

        float2 v[8];
#pragma unroll
        for (int j = 0; j < 8; ++j) {
            int src = sd[j] & 0xFFFF;
            v[j] = *reinterpret_cast<const float2*>(xin + (size_t)src * D + 2 * lane);
        }

        if (bt < 7) {
            sdA = sdp[2 * bt + 2];
            sdB = sdp[2 * bt + 3];
            wA = wp[2 * bt + 2];
            wB = wp[2 * bt + 3];
        }

#pragma unroll
        for (int j = 0; j < 8; ++j) {
            int d = ((unsigned)sd[j]) >> 16;
            if (d != cur) {
                if (cur >= 0) flush_v2(aggr, cur, lane, acc);
                acc = make_float2(0.f, 0.f);
                cur = d;
            }
            acc.x += v[j].x * wt[j];
            acc.y += v[j].y * wt[j];
        }
    }
    if (cur >= 0) flush_v2(aggr, cur, lane, acc);
}

// ---------------------------------------------------------------------------
// Update (R8/R10 proven): xout = l2norm( concat(l2norm(aggr), x) @ W + b )
// TB=64, 4 rows x 4 cols per thread, FFMA2 GEMM, 391 blocks, 3 CTA/SM.
// Zeroes aggr rows after read (replaces per-layer memset).
// ---------------------------------------------------------------------------
#define TB 64
#define HSTR 132
#define N_TILES ((N_NODES + TB - 1) / TB)   // 782
#define SMEM_BYTES ((128 * 64 + TB * HSTR) * 4)

__device__ __forceinline__ u64 fma2(u64 a, u64 b, u64 c) {
    u64 d;
    asm("fma.rn.f32x2 %0, %1, %2, %3;" : "=l"(d) : "l"(a), "l"(b), "l"(c));
    return d;
}
__device__ __forceinline__ u64 bcast2(float x) {
    u64 d;
    asm("mov.b64 %0, {%1, %1};" : "=l"(d) : "f"(x));
    return d;
}
__device__ __forceinline__ u64 pack2(float lo, float hi) {
    u64 d;
    asm("mov.b64 %0, {%1, %2};" : "=l"(d) : "f"(lo), "f"(hi));
    return d;
}
__device__ __forceinline__ float2 unpack2(u64 v) {
    float lo, hi;
    asm("mov.b64 {%0, %1}, %2;" : "=f"(lo), "=f"(hi) : "l"(v));
    return make_float2(lo, hi);
}

__global__ void __launch_bounds__(256, 3)
update_kernel(float* __restrict__ aggr,
              const float* __restrict__ xin,
              const float* __restrict__ W,
              const float* __restrict__ b,
              float* __restrict__ xout) {
    extern __shared__ float smem[];
    float* W_s = smem;             // 128*64
    float* h_s = smem + 128 * 64;  // TB x HSTR

    int tid = threadIdx.x;
    int lane = tid & 31;
    int warp = tid >> 5;

    {
        const float4* Wv = reinterpret_cast<const float4*>(W);
        float4* Wsv = reinterpret_cast<float4*>(W_s);
#pragma unroll
        for (int i = 0; i < 8; ++i)
            Wsv[tid + i * 256] = Wv[tid + i * 256];
    }

    int tx = tid & 15, ty = tid >> 4;
    u64 bias0 = pack2(b[tx * 4 + 0], b[tx * 4 + 1]);
    u64 bias1 = pack2(b[tx * 4 + 2], b[tx * 4 + 3]);

    int p1_node = (warp << 3) + (lane >> 2);
    int p1_p = lane & 3;

    for (int tile = blockIdx.x; tile < N_TILES; tile += gridDim.x) {
        __syncthreads();

        // ---- Phase 1: load aggr + x, l2norm(aggr), fill h_s, zero aggr rows
        {
            int node = tile * TB + p1_node;
            float4 a[4], xv[4];
            if (node < N_NODES) {
                const float4* ar = reinterpret_cast<const float4*>(aggr + (size_t)node * D);
                const float4* xr = reinterpret_cast<const float4*>(xin + (size_t)node * D);
#pragma unroll
                for (int j = 0; j < 4; ++j) {
                    a[j]  = ar[p1_p + j * 4];
                    xv[j] = xr[p1_p + j * 4];
                }
                float4 z = make_float4(0.f, 0.f, 0.f, 0.f);
                float4* aw = reinterpret_cast<float4*>(aggr + (size_t)node * D);
#pragma unroll
                for (int j = 0; j < 4; ++j) aw[p1_p + j * 4] = z;
            } else {
#pragma unroll
                for (int j = 0; j < 4; ++j) {
                    a[j] = make_float4(0.f, 0.f, 0.f, 0.f);
                    xv[j] = a[j];
                }
            }
            float ss = 0.f;
#pragma unroll
            for (int j = 0; j < 4; ++j)
                ss += a[j].x * a[j].x + a[j].y * a[j].y
                    + a[j].z * a[j].z + a[j].w * a[j].w;
            ss += __shfl_xor_sync(0xFFFFFFFFu, ss, 1);
            ss += __shfl_xor_sync(0xFFFFFFFFu, ss, 2);
            float inv = 1.0f / fmaxf(sqrtf(ss), 1e-12f);

            float4* hr = reinterpret_cast<float4*>(h_s + p1_node * HSTR);
#pragma unroll
            for (int j = 0; j < 4; ++j) {
                float4 an;
                an.x = a[j].x * inv; an.y = a[j].y * inv;
                an.z = a[j].z * inv; an.w = a[j].w * inv;
                hr[p1_p + j * 4] = an;
                hr[16 + p1_p + j * 4] = xv[j];
            }
        }
        __syncthreads();

        // ---- Phase 2: GEMM with packed f32x2 FFMA (4 rows x 4 cols / thread)
        u64 acc2[4][2];
#pragma unroll
        for (int i = 0; i < 4; ++i) { acc2[i][0] = bias0; acc2[i][1] = bias1; }

        const float* hbase = h_s + (ty * 4) * HSTR;
#pragma unroll 4
        for (int k = 0; k < 128; k += 4) {
            ulonglong2 wq0 = *reinterpret_cast<const ulonglong2*>(W_s + (k + 0) * 64 + tx * 4);
            ulonglong2 wq1 = *reinterpret_cast<const ulonglong2*>(W_s + (k + 1) * 64 + tx * 4);
            ulonglong2 wq2 = *reinterpret_cast<const ulonglong2*>(W_s + (k + 2) * 64 + tx * 4);
            ulonglong2 wq3 = *reinterpret_cast<const ulonglong2*>(W_s + (k + 3) * 64 + tx * 4);
#pragma unroll
            for (int i = 0; i < 4; ++i) {
                float4 h4 = *reinterpret_cast<const float4*>(hbase + i * HSTR + k);
                u64 hx = bcast2(h4.x);
                acc2[i][0] = fma2(hx, wq0.x, acc2[i][0]);
                acc2[i][1] = fma2(hx, wq0.y, acc2[i][1]);
                u64 hy = bcast2(h4.y);
                acc2[i][0] = fma2(hy, wq1.x, acc2[i][0]);
                acc2[i][1] = fma2(hy, wq1.y, acc2[i][1]);
                u64 hz = bcast2(h4.z);
                acc2[i][0] = fma2(hz, wq2.x, acc2[i][0]);
                acc2[i][1] = fma2(hz, wq2.y, acc2[i][1]);
                u64 hw = bcast2(h4.w);
                acc2[i][0] = fma2(hw, wq3.x, acc2[i][0]);
                acc2[i][1] = fma2(hw, wq3.y, acc2[i][1]);
            }
        }

        // ---- Phase 3: row l2norm across 16 tx threads, store
#pragma unroll
        for (int i = 0; i < 4; ++i) {
            int r = ty * 4 + i;
            int node = tile * TB + r;
            float2 c0 = unpack2(acc2[i][0]);
            float2 c1 = unpack2(acc2[i][1]);
            float ss = c0.x * c0.x + c0.y * c0.y + c1.x * c1.x + c1.y * c1.y;
#pragma unroll
            for (int m = 8; m; m >>= 1) ss += __shfl_xor_sync(0xFFFFFFFFu, ss, m);
            float inv = 1.0f / fmaxf(sqrtf(ss), 1e-12f);
            if (node < N_NODES) {
                float4 o;
                o.x = c0.x * inv; o.y = c0.y * inv;
                o.z = c1.x * inv; o.w = c1.y * inv;
                *reinterpret_cast<float4*>(xout + (size_t)node * D + tx * 4) = o;
            }
        }
    }
}

// ---------------------------------------------------------------------------
extern "C" void kernel_launch(void* const* d_in, const int* in_sizes, int n_in,
                              void* d_out, int out_size) {
    const float* x  = (const float*)d_in[0];
    const int* ei   = (const int*)d_in[1];
    const float* ew = (const float*)d_in[2];
    const float* W  = (const float*)d_in[3];
    const float* b  = (const float*)d_in[4];
    float* out      = (float*)d_out;

    float *aggr, *buf0, *buf1;
    int* deg;
    cudaGetSymbolAddress((void**)&aggr, g_aggr);
    cudaGetSymbolAddress((void**)&buf0, g_buf0);
    cudaGetSymbolAddress((void**)&buf1, g_buf1);
    cudaGetSymbolAddress((void**)&deg, g_deg);

    cudaFuncSetAttribute(update_kernel,
                         cudaFuncAttributeMaxDynamicSharedMemorySize,
                         SMEM_BYTES);

    const int edge_blocks = (N_EDGES + 255) / 256;
    const int agg_blocks = (N_SPANS + 7) / 8;   // 1563
    const int upd_blocks = 391;                 // 782 tiles / exactly 2 each

    // CSR build (once per call)
    cudaMemsetAsync(deg, 0, N_NODES * sizeof(int), 0);
    hist_kernel<<<edge_blocks, 256>>>(ei);
    scan_kernel<<<1, SCAN_T>>>();
    permute_kernel<<<edge_blocks, 256>>>(ei, ew);

    // aggr starts zero; update re-zeros it each layer
    cudaMemsetAsync(aggr, 0, (size_t)N_NODES * D * sizeof(float), 0);

    const float* cur = x;
    for (int l = 0; l < N_LAYERS; ++l) {
        aggregate_kernel<<<agg_blocks, 256>>>(cur, aggr);
        float* nxt = (l == N_LAYERS - 1) ? out : ((l & 1) ? buf1 : buf0);
        update_kernel<<<upd_blocks, 256, SMEM_BYTES>>>(
            aggr, cur, W + (size_t)l * 2 * D * D, b + (size_t)l * D, nxt);
        cur = nxt;
    }
}

// round 14
// speedup vs baseline: 1.6345x; 1.0062x over previous
#include <cuda_runtime.h>
#include <cuda_bf16.h>
#include <stdint.h>

#define N_NODES 50000
#define N_EDGES 800000
#define D 64
#define N_LAYERS 12

typedef unsigned long long u64;

__device__ float g_aggr[N_NODES * D];
__device__ float g_buf0[N_NODES * D];
__device__ float g_buf1[N_NODES * D];
// CSR-sorted edge arrays (built once per launch)
__device__ int   g_deg[N_NODES];
__device__ int   g_cur[N_NODES];
__device__ int   g_sd[N_EDGES];    // packed: src | (dst << 16)
__device__ float g_w[N_EDGES];

// ===========================================================================
// CSR build: histogram -> scan -> permute (sort edges by dst, pack src|dst)
// ===========================================================================
__global__ void hist_kernel(const int* __restrict__ ei) {
    int e = blockIdx.x * blockDim.x + threadIdx.x;
    if (e < N_EDGES) atomicAdd(&g_deg[ei[N_EDGES + e]], 1);
}

#define SCAN_T 1024
#define SCAN_C 49
__global__ void scan_kernel() {
    __shared__ int part[SCAN_T];
    int t = threadIdx.x;
    int base = t * SCAN_C;
    int s = 0;
    for (int j = 0; j < SCAN_C; ++j) {
        int idx = base + j;
        if (idx < N_NODES) s += g_deg[idx];
    }
    part[t] = s;
    __syncthreads();
    for (int off = 1; off < SCAN_T; off <<= 1) {
        int v = (t >= off) ? part[t - off] : 0;
        __syncthreads();
        part[t] += v;
        __syncthreads();
    }
    int run = (t > 0) ? part[t - 1] : 0;
    for (int j = 0; j < SCAN_C; ++j) {
        int idx = base + j;
        if (idx < N_NODES) {
            g_cur[idx] = run;
            run += g_deg[idx];
        }
    }
}

__global__ void permute_kernel(const int* __restrict__ ei,
                               const float* __restrict__ ew) {
    int e = blockIdx.x * blockDim.x + threadIdx.x;
    if (e >= N_EDGES) return;
    int d = ei[N_EDGES + e];
    int pos = atomicAdd(&g_cur[d], 1);
    g_sd[pos] = ei[e] | (d << 16);
    g_w[pos] = ew[e];
}

// ===========================================================================
// Aggregation (R11/R12 winner, unchanged)
// ===========================================================================
#define AGG_SPAN 64
#define N_SPANS (N_EDGES / AGG_SPAN)

__device__ __forceinline__ void flush_v2(float* aggr, int dstn, int lane, float2 a) {
    float* p = aggr + (size_t)dstn * D + 2 * lane;
    u64 gp = (u64)__cvta_generic_to_global(p);
    asm volatile("red.global.add.v2.f32 [%0], {%1,%2};"
                 :: "l"(gp), "f"(a.x), "f"(a.y) : "memory");
}

__global__ void __launch_bounds__(256, 4)
aggregate_kernel(const float* __restrict__ xin, float* __restrict__ aggr) {
    int warp = threadIdx.x >> 5, lane = threadIdx.x & 31;
    int span = blockIdx.x * 8 + warp;
    if (span >= N_SPANS) return;
    int e0 = span * AGG_SPAN;

    const int4* sdp = reinterpret_cast<const int4*>(g_sd + e0);
    const float4* wp = reinterpret_cast<const float4*>(g_w + e0);

    int4 sdA = sdp[0], sdB = sdp[1];
    float4 wA = wp[0], wB = wp[1];

    float2 acc = make_float2(0.f, 0.f);
    int cur = -1;

#pragma unroll
    for (int bt = 0; bt < 8; ++bt) {
        int sd[8] = {sdA.x, sdA.y, sdA.z, sdA.w, sdB.x, sdB.y, sdB.z, sdB.w};
        float wt[8] = {wA.x, wA.y, wA.z, wA.w, wB.x, wB.y, wB.z, wB.w};

        float2 v[8];
#pragma unroll
        for (int j = 0; j < 8; ++j) {
            int src = sd[j] & 0xFFFF;
            v[j] = *reinterpret_cast<const float2*>(xin + (size_t)src * D + 2 * lane);
        }

        if (bt < 7) {
            sdA = sdp[2 * bt + 2];
            sdB = sdp[2 * bt + 3];
            wA = wp[2 * bt + 2];
            wB = wp[2 * bt + 3];
        }

#pragma unroll
        for (int j = 0; j < 8; ++j) {
            int d = ((unsigned)sd[j]) >> 16;
            if (d != cur) {
                if (cur >= 0) flush_v2(aggr, cur, lane, acc);
                acc = make_float2(0.f, 0.f);
                cur = d;
            }
            acc.x += v[j].x * wt[j];
            acc.y += v[j].y * wt[j];
        }
    }
    if (cur >= 0) flush_v2(aggr, cur, lane, acc);
}

// ===========================================================================
// Update via mma.sync m16n8k16 bf16 (sm_80+ path — no 'a' suffix needed).
// Split precision: h and W in bf16 (hi,lo); 3 MMAs per fragment, fp32 acc.
// One 64-node tile per CTA, 128 threads / 4 warps; warp w owns rows
// [16w,16w+16) x all 64 cols. h,W staged in smem, ldmatrix fragments.
// ===========================================================================
#define UTB 64
#define UN_TILES ((N_NODES + UTB - 1) / UTB)   // 782

#define HSTR2 136                // bf16 per h row (272 B; 272%128=16 -> ldsm ok)
#define WSTR2 72                 // bf16 per W row (144 B; 144%128=16 -> ldsm ok)
#define SM_BIAS 0
#define SM_HHI  256
#define SM_HLO  (SM_HHI + UTB * HSTR2 * 2)        // +17408
#define SM_WHI  (SM_HLO + UTB * HSTR2 * 2)        // +17408
#define SM_WLO  (SM_WHI + 128 * WSTR2 * 2)        // +18432
#define SM_TOTAL (SM_WLO + 128 * WSTR2 * 2 + 128) // ~72 KB

__device__ __forceinline__ uint32_t smem_u32(const void* p) {
    uint32_t a;
    asm("{ .reg .u64 t; cvta.to.shared.u64 t, %1; cvt.u32.u64 %0, t; }"
        : "=r"(a) : "l"(p));
    return a;
}
__device__ __forceinline__ void ldsm_x4(uint32_t addr, uint32_t& r0, uint32_t& r1,
                                        uint32_t& r2, uint32_t& r3) {
    asm volatile("ldmatrix.sync.aligned.m8n8.x4.shared.b16 {%0,%1,%2,%3}, [%4];"
                 : "=r"(r0), "=r"(r1), "=r"(r2), "=r"(r3) : "r"(addr));
}
__device__ __forceinline__ void ldsm_x4t(uint32_t addr, uint32_t& r0, uint32_t& r1,
                                         uint32_t& r2, uint32_t& r3) {
    asm volatile("ldmatrix.sync.aligned.m8n8.x4.trans.shared.b16 {%0,%1,%2,%3}, [%4];"
                 : "=r"(r0), "=r"(r1), "=r"(r2), "=r"(r3) : "r"(addr));
}
__device__ __forceinline__ void mma_bf16(float* c, uint32_t a0, uint32_t a1,
                                         uint32_t a2, uint32_t a3,
                                         uint32_t b0, uint32_t b1) {
    asm volatile(
        "mma.sync.aligned.m16n8k16.row.col.f32.bf16.bf16.f32 "
        "{%0,%1,%2,%3}, {%4,%5,%6,%7}, {%8,%9}, {%0,%1,%2,%3};"
        : "+f"(c[0]), "+f"(c[1]), "+f"(c[2]), "+f"(c[3])
        : "r"(a0), "r"(a1), "r"(a2), "r"(a3), "r"(b0), "r"(b1));
}
__device__ __forceinline__ uint32_t split_pack_hi(float f0, float f1,
                                                  float& r0, float& r1) {
    __nv_bfloat16 h0 = __float2bfloat16(f0);
    __nv_bfloat16 h1 = __float2bfloat16(f1);
    r0 = f0 - __bfloat162float(h0);
    r1 = f1 - __bfloat162float(h1);
    return ((uint32_t)__bfloat16_as_ushort(h1) << 16) | (uint32_t)__bfloat16_as_ushort(h0);
}
__device__ __forceinline__ uint32_t pack_bf16(float f0, float f1) {
    __nv_bfloat16 h0 = __float2bfloat16(f0);
    __nv_bfloat16 h1 = __float2bfloat16(f1);
    return ((uint32_t)__bfloat16_as_ushort(h1) << 16) | (uint32_t)__bfloat16_as_ushort(h0);
}

__global__ void __launch_bounds__(128)
update_kernel(float* __restrict__ aggr,
              const float* __restrict__ xin,
              const float* __restrict__ W,   // [128][64] layer slice
              const float* __restrict__ b,   // [64]
              float* __restrict__ xout) {
    extern __shared__ char smem[];
    uint32_t sbase = smem_u32(smem);
    int tid = threadIdx.x;
    int lane = tid & 31;
    int wid = tid >> 5;
    int n0 = blockIdx.x * UTB;

    // --- Stage W (split bf16 hi/lo) + bias into smem
    {
        float* bias_s = reinterpret_cast<float*>(smem + SM_BIAS);
        if (tid < 64) bias_s[tid] = b[tid];
        const float4* wrow = reinterpret_cast<const float4*>(W + tid * 64);
        uint32_t* whi = reinterpret_cast<uint32_t*>(smem + SM_WHI + tid * (WSTR2 * 2));
        uint32_t* wlo = reinterpret_cast<uint32_t*>(smem + SM_WLO + tid * (WSTR2 * 2));
#pragma unroll
        for (int i = 0; i < 16; ++i) {
            float4 t = wrow[i];
            float l0, l1, l2, l3;
            uint32_t h01 = split_pack_hi(t.x, t.y, l0, l1);
            uint32_t h23 = split_pack_hi(t.z, t.w, l2, l3);
            whi[2 * i]     = h01;
            whi[2 * i + 1] = h23;
            wlo[2 * i]     = pack_bf16(l0, l1);
            wlo[2 * i + 1] = pack_bf16(l2, l3);
        }
    }

    // --- Phase 1: h = concat(l2norm(aggr), x) split to bf16 hi/lo in smem.
    // thread: row r = tid>>1, half = tid&1 (32 cols of each of aggr & x).
    {
        int r = tid >> 1;
        int half = tid & 1;
        int node = n0 + r;
        float av[32], xv[32];
        if (node < N_NODES) {
            const float4* ar = reinterpret_cast<const float4*>(
                aggr + (size_t)node * D + half * 32);
            const float4* xr = reinterpret_cast<const float4*>(
                xin + (size_t)node * D + half * 32);
#pragma unroll
            for (int i = 0; i < 8; ++i) {
                float4 t = ar[i];
                av[4 * i] = t.x; av[4 * i + 1] = t.y;
                av[4 * i + 2] = t.z; av[4 * i + 3] = t.w;
                float4 u = xr[i];
                xv[4 * i] = u.x; xv[4 * i + 1] = u.y;
                xv[4 * i + 2] = u.z; xv[4 * i + 3] = u.w;
            }
            // zero aggr rows for next layer's aggregation
            float4 z = make_float4(0.f, 0.f, 0.f, 0.f);
            float4* aw = reinterpret_cast<float4*>(aggr + (size_t)node * D + half * 32);
#pragma unroll
            for (int i = 0; i < 8; ++i) aw[i] = z;
        } else {
#pragma unroll
            for (int i = 0; i < 32; ++i) { av[i] = 0.f; xv[i] = 0.f; }
        }
        float ss = 0.f;
#pragma unroll
        for (int i = 0; i < 32; ++i) ss += av[i] * av[i];
        ss += __shfl_xor_sync(0xFFFFFFFFu, ss, 1);
        float inv = 1.0f / fmaxf(sqrtf(ss), 1e-12f);

        uint32_t* hhi = reinterpret_cast<uint32_t*>(smem + SM_HHI + r * (HSTR2 * 2));
        uint32_t* hlo = reinterpret_cast<uint32_t*>(smem + SM_HLO + r * (HSTR2 * 2));
        int c0 = half * 16;           // uint32 index (2 bf16 each)
#pragma unroll
        for (int i = 0; i < 16; ++i) {
            float f0 = av[2 * i] * inv, f1 = av[2 * i + 1] * inv;
            float l0, l1;
            uint32_t h = split_pack_hi(f0, f1, l0, l1);
            hhi[c0 + i] = h;
            hlo[c0 + i] = pack_bf16(l0, l1);
        }
#pragma unroll
        for (int i = 0; i < 16; ++i) {
            float l0, l1;
            uint32_t h = split_pack_hi(xv[2 * i], xv[2 * i + 1], l0, l1);
            hhi[32 + c0 + i] = h;
            hlo[32 + c0 + i] = pack_bf16(l0, l1);
        }
    }
    __syncthreads();

    // --- Phase 2: MMA. warp owns rows [16*wid, +16), cols 0..63, K=128.
    float acc[8][4];
#pragma unroll
    for (int j = 0; j < 8; ++j)
#pragma unroll
        for (int q = 0; q < 4; ++q) acc[j][q] = 0.f;

    {
        int lane15 = lane & 15;
        int laneHi = (lane >> 4) & 1;
        uint32_t a_hi = sbase + SM_HHI + (wid * 16 + lane15) * (HSTR2 * 2) + laneHi * 16;
        uint32_t a_lo = sbase + SM_HLO + (wid * 16 + lane15) * (HSTR2 * 2) + laneHi * 16;
        uint32_t b_hi = sbase + SM_WHI + lane15 * (WSTR2 * 2) + laneHi * 16;
        uint32_t b_lo = sbase + SM_WLO + lane15 * (WSTR2 * 2) + laneHi * 16;

#pragma unroll 2
        for (int ks = 0; ks < 8; ++ks) {
            uint32_t ah0, ah1, ah2, ah3, al0, al1, al2, al3;
            ldsm_x4(a_hi + ks * 32, ah0, ah1, ah2, ah3);
            ldsm_x4(a_lo + ks * 32, al0, al1, al2, al3);
            uint32_t bk = ks * 16 * (WSTR2 * 2);
#pragma unroll
            for (int ch = 0; ch < 4; ++ch) {
                uint32_t bh0, bh1, bh2, bh3, bl0, bl1, bl2, bl3;
                ldsm_x4t(b_hi + bk + ch * 32, bh0, bh1, bh2, bh3);
                ldsm_x4t(b_lo + bk + ch * 32, bl0, bl1, bl2, bl3);
                mma_bf16(acc[2 * ch],     ah0, ah1, ah2, ah3, bh0, bh1);
                mma_bf16(acc[2 * ch],     ah0, ah1, ah2, ah3, bl0, bl1);
                mma_bf16(acc[2 * ch],     al0, al1, al2, al3, bh0, bh1);
                mma_bf16(acc[2 * ch + 1], ah0, ah1, ah2, ah3, bh2, bh3);
                mma_bf16(acc[2 * ch + 1], ah0, ah1, ah2, ah3, bl2, bl3);
                mma_bf16(acc[2 * ch + 1], al0, al1, al2, al3, bh2, bh3);
            }
        }
    }

    // --- Phase 3: bias + per-row l2norm + store.
    // c[j][0],c[j][1]: row = 16*wid + (lane>>2), cols 8j + (lane&3)*2 +{0,1}
    // c[j][2],c[j][3]: row + 8, same cols
    {
        const float* bias_s = reinterpret_cast<const float*>(smem + SM_BIAS);
        float ss1 = 0.f, ss2 = 0.f;
#pragma unroll
        for (int j = 0; j < 8; ++j) {
            float2 bb = *reinterpret_cast<const float2*>(bias_s + 8 * j + (lane & 3) * 2);
            acc[j][0] += bb.x; acc[j][1] += bb.y;
            acc[j][2] += bb.x; acc[j][3] += bb.y;
            ss1 += acc[j][0] * acc[j][0] + acc[j][1] * acc[j][1];
            ss2 += acc[j][2] * acc[j][2] + acc[j][3] * acc[j][3];
        }
        ss1 += __shfl_xor_sync(0xFFFFFFFFu, ss1, 1);
        ss1 += __shfl_xor_sync(0xFFFFFFFFu, ss1, 2);
        ss2 += __shfl_xor_sync(0xFFFFFFFFu, ss2, 1);
        ss2 += __shfl_xor_sync(0xFFFFFFFFu, ss2, 2);
        float inv1 = 1.0f / fmaxf(sqrtf(ss1), 1e-12f);
        float inv2 = 1.0f / fmaxf(sqrtf(ss2), 1e-12f);

        int r1 = n0 + wid * 16 + (lane >> 2);
        int r2 = r1 + 8;
        int coff = (lane & 3) * 2;
        if (r1 < N_NODES) {
            float* o = xout + (size_t)r1 * D + coff;
#pragma unroll
            for (int j = 0; j < 8; ++j) {
                float2 t; t.x = acc[j][0] * inv1; t.y = acc[j][1] * inv1;
                *reinterpret_cast<float2*>(o + 8 * j) = t;
            }
        }
        if (r2 < N_NODES) {
            float* o = xout + (size_t)r2 * D + coff;
#pragma unroll
            for (int j = 0; j < 8; ++j) {
                float2 t; t.x = acc[j][2] * inv2; t.y = acc[j][3] * inv2;
                *reinterpret_cast<float2*>(o + 8 * j) = t;
            }
        }
    }
}

// ---------------------------------------------------------------------------
extern "C" void kernel_launch(void* const* d_in, const int* in_sizes, int n_in,
                              void* d_out, int out_size) {
    const float* x  = (const float*)d_in[0];
    const int* ei   = (const int*)d_in[1];
    const float* ew = (const float*)d_in[2];
    const float* W  = (const float*)d_in[3];
    const float* b  = (const float*)d_in[4];
    float* out      = (float*)d_out;

    float *aggr, *buf0, *buf1;
    int* deg;
    cudaGetSymbolAddress((void**)&aggr, g_aggr);
    cudaGetSymbolAddress((void**)&buf0, g_buf0);
    cudaGetSymbolAddress((void**)&buf1, g_buf1);
    cudaGetSymbolAddress((void**)&deg, g_deg);

    cudaFuncSetAttribute(update_kernel,
                         cudaFuncAttributeMaxDynamicSharedMemorySize,
                         SM_TOTAL);

    const int edge_blocks = (N_EDGES + 255) / 256;
    const int agg_blocks = (N_SPANS + 7) / 8;   // 1563

    // CSR build (once per call)
    cudaMemsetAsync(deg, 0, N_NODES * sizeof(int), 0);
    hist_kernel<<<edge_blocks, 256>>>(ei);
    scan_kernel<<<1, SCAN_T>>>();
    permute_kernel<<<edge_blocks, 256>>>(ei, ew);

    // aggr starts zero; update re-zeros it each layer
    cudaMemsetAsync(aggr, 0, (size_t)N_NODES * D * sizeof(float), 0);

    const float* cur = x;
    for (int l = 0; l < N_LAYERS; ++l) {
        aggregate_kernel<<<agg_blocks, 256>>>(cur, aggr);
        float* nxt = (l == N_LAYERS - 1) ? out : ((l & 1) ? buf1 : buf0);
        update_kernel<<<UN_TILES, 128, SM_TOTAL>>>(
            aggr, cur, W + (size_t)l * 2 * D * D, b + (size_t)l * D, nxt);
        cur = nxt;
    }
}

// round 15
// speedup vs baseline: 1.7057x; 1.0435x over previous
#include <cuda_runtime.h>
#include <cuda_bf16.h>
#include <stdint.h>

#define N_NODES 50000
#define N_EDGES 800000
#define D 64
#define N_LAYERS 12

typedef unsigned long long u64;

__device__ float g_aggr[N_NODES * D];
__device__ float g_buf0[N_NODES * D];
__device__ float g_buf1[N_NODES * D];
// CSR-sorted edge arrays (built once per launch)
__device__ int   g_deg[N_NODES];
__device__ int   g_cur[N_NODES];
__device__ int   g_sd[N_EDGES];    // packed: src | (dst << 16)
__device__ float g_w[N_EDGES];

// ===========================================================================
// CSR build: histogram -> scan -> permute (sort edges by dst, pack src|dst)
// ===========================================================================
__global__ void hist_kernel(const int* __restrict__ ei) {
    int e = blockIdx.x * blockDim.x + threadIdx.x;
    if (e < N_EDGES) atomicAdd(&g_deg[ei[N_EDGES + e]], 1);
}

#define SCAN_T 1024
#define SCAN_C 49
__global__ void scan_kernel() {
    __shared__ int part[SCAN_T];
    int t = threadIdx.x;
    int base = t * SCAN_C;
    int s = 0;
    for (int j = 0; j < SCAN_C; ++j) {
        int idx = base + j;
        if (idx < N_NODES) s += g_deg[idx];
    }
    part[t] = s;
    __syncthreads();
    for (int off = 1; off < SCAN_T; off <<= 1) {
        int v = (t >= off) ? part[t - off] : 0;
        __syncthreads();
        part[t] += v;
        __syncthreads();
    }
    int run = (t > 0) ? part[t - 1] : 0;
    for (int j = 0; j < SCAN_C; ++j) {
        int idx = base + j;
        if (idx < N_NODES) {
            g_cur[idx] = run;
            run += g_deg[idx];
        }
    }
}

__global__ void permute_kernel(const int* __restrict__ ei,
                               const float* __restrict__ ew) {
    int e = blockIdx.x * blockDim.x + threadIdx.x;
    if (e >= N_EDGES) return;
    int d = ei[N_EDGES + e];
    int pos = atomicAdd(&g_cur[d], 1);
    g_sd[pos] = ei[e] | (d << 16);
    g_w[pos] = ew[e];
}

// ===========================================================================
// Aggregation (R11/R12 winner, unchanged)
// ===========================================================================
#define AGG_SPAN 64
#define N_SPANS (N_EDGES / AGG_SPAN)

__device__ __forceinline__ void flush_v2(float* aggr, int dstn, int lane, float2 a) {
    float* p = aggr + (size_t)dstn * D + 2 * lane;
    u64 gp = (u64)__cvta_generic_to_global(p);
    asm volatile("red.global.add.v2.f32 [%0], {%1,%2};"
                 :: "l"(gp), "f"(a.x), "f"(a.y) : "memory");
}

__global__ void __launch_bounds__(256, 4)
aggregate_kernel(const float* __restrict__ xin, float* __restrict__ aggr) {
    int warp = threadIdx.x >> 5, lane = threadIdx.x & 31;
    int span = blockIdx.x * 8 + warp;
    if (span >= N_SPANS) return;
    int e0 = span * AGG_SPAN;

    const int4* sdp = reinterpret_cast<const int4*>(g_sd + e0);
    const float4* wp = reinterpret_cast<const float4*>(g_w + e0);

    int4 sdA = sdp[0], sdB = sdp[1];
    float4 wA = wp[0], wB = wp[1];

    float2 acc = make_float2(0.f, 0.f);
    int cur = -1;

#pragma unroll
    for (int bt = 0; bt < 8; ++bt) {
        int sd[8] = {sdA.x, sdA.y, sdA.z, sdA.w, sdB.x, sdB.y, sdB.z, sdB.w};
        float wt[8] = {wA.x, wA.y, wA.z, wA.w, wB.x, wB.y, wB.z, wB.w};

        float2 v[8];
#pragma unroll
        for (int j = 0; j < 8; ++j) {
            int src = sd[j] & 0xFFFF;
            v[j] = *reinterpret_cast<const float2*>(xin + (size_t)src * D + 2 * lane);
        }

        if (bt < 7) {
            sdA = sdp[2 * bt + 2];
            sdB = sdp[2 * bt + 3];
            wA = wp[2 * bt + 2];
            wB = wp[2 * bt + 3];
        }

#pragma unroll
        for (int j = 0; j < 8; ++j) {
            int d = ((unsigned)sd[j]) >> 16;
            if (d != cur) {
                if (cur >= 0) flush_v2(aggr, cur, lane, acc);
                acc = make_float2(0.f, 0.f);
                cur = d;
            }
            acc.x += v[j].x * wt[j];
            acc.y += v[j].y * wt[j];
        }
    }
    if (cur >= 0) flush_v2(aggr, cur, lane, acc);
}

// ===========================================================================
// Update via mma.sync m16n8k16 bf16, split precision (hi,lo), fp32 acc.
// R15: 128-node tile, 256 threads / 8 MMA warps, 2 CTA/SM, 1.32 waves.
// Warp w owns rows [16w,16w+16) x all 64 cols.
// ===========================================================================
#define UTB 128
#define UN_TILES ((N_NODES + UTB - 1) / UTB)   // 391

#define HSTR2 136                // bf16 per h row (272 B; 272%128=16 -> ldsm ok)
#define WSTR2 72                 // bf16 per W row (144 B; 144%128=16 -> ldsm ok)
#define SM_BIAS 0
#define SM_HHI  256
#define SM_HLO  (SM_HHI + UTB * HSTR2 * 2)        // +34816
#define SM_WHI  (SM_HLO + UTB * HSTR2 * 2)        // +34816
#define SM_WLO  (SM_WHI + 128 * WSTR2 * 2)        // +18432
#define SM_TOTAL (SM_WLO + 128 * WSTR2 * 2 + 128) // ~107 KB

__device__ __forceinline__ uint32_t smem_u32(const void* p) {
    uint32_t a;
    asm("{ .reg .u64 t; cvta.to.shared.u64 t, %1; cvt.u32.u64 %0, t; }"
        : "=r"(a) : "l"(p));
    return a;
}
__device__ __forceinline__ void ldsm_x4(uint32_t addr, uint32_t& r0, uint32_t& r1,
                                        uint32_t& r2, uint32_t& r3) {
    asm volatile("ldmatrix.sync.aligned.m8n8.x4.shared.b16 {%0,%1,%2,%3}, [%4];"
                 : "=r"(r0), "=r"(r1), "=r"(r2), "=r"(r3) : "r"(addr));
}
__device__ __forceinline__ void ldsm_x4t(uint32_t addr, uint32_t& r0, uint32_t& r1,
                                         uint32_t& r2, uint32_t& r3) {
    asm volatile("ldmatrix.sync.aligned.m8n8.x4.trans.shared.b16 {%0,%1,%2,%3}, [%4];"
                 : "=r"(r0), "=r"(r1), "=r"(r2), "=r"(r3) : "r"(addr));
}
__device__ __forceinline__ void mma_bf16(float* c, uint32_t a0, uint32_t a1,
                                         uint32_t a2, uint32_t a3,
                                         uint32_t b0, uint32_t b1) {
    asm volatile(
        "mma.sync.aligned.m16n8k16.row.col.f32.bf16.bf16.f32 "
        "{%0,%1,%2,%3}, {%4,%5,%6,%7}, {%8,%9}, {%0,%1,%2,%3};"
        : "+f"(c[0]), "+f"(c[1]), "+f"(c[2]), "+f"(c[3])
        : "r"(a0), "r"(a1), "r"(a2), "r"(a3), "r"(b0), "r"(b1));
}
__device__ __forceinline__ uint32_t split_pack_hi(float f0, float f1,
                                                  float& r0, float& r1) {
    __nv_bfloat16 h0 = __float2bfloat16(f0);
    __nv_bfloat16 h1 = __float2bfloat16(f1);
    r0 = f0 - __bfloat162float(h0);
    r1 = f1 - __bfloat162float(h1);
    return ((uint32_t)__bfloat16_as_ushort(h1) << 16) | (uint32_t)__bfloat16_as_ushort(h0);
}
__device__ __forceinline__ uint32_t pack_bf16(float f0, float f1) {
    __nv_bfloat16 h0 = __float2bfloat16(f0);
    __nv_bfloat16 h1 = __float2bfloat16(f1);
    return ((uint32_t)__bfloat16_as_ushort(h1) << 16) | (uint32_t)__bfloat16_as_ushort(h0);
}

__global__ void __launch_bounds__(256)
update_kernel(float* __restrict__ aggr,
              const float* __restrict__ xin,
              const float* __restrict__ W,   // [128][64] layer slice
              const float* __restrict__ b,   // [64]
              float* __restrict__ xout) {
    extern __shared__ char smem[];
    uint32_t sbase = smem_u32(smem);
    int tid = threadIdx.x;
    int lane = tid & 31;
    int wid = tid >> 5;
    int n0 = blockIdx.x * UTB;

    // --- Stage W (split bf16 hi/lo) + bias into smem.
    // Thread handles half a W row: row = tid>>1, float4s [half*8, half*8+8)
    {
        float* bias_s = reinterpret_cast<float*>(smem + SM_BIAS);
        if (tid < 64) bias_s[tid] = b[tid];
        int wr = tid >> 1;
        int wh = tid & 1;
        const float4* wrow = reinterpret_cast<const float4*>(W + wr * 64) + wh * 8;
        uint32_t* whi = reinterpret_cast<uint32_t*>(smem + SM_WHI + wr * (WSTR2 * 2)) + wh * 16;
        uint32_t* wlo = reinterpret_cast<uint32_t*>(smem + SM_WLO + wr * (WSTR2 * 2)) + wh * 16;
#pragma unroll
        for (int i = 0; i < 8; ++i) {
            float4 t = wrow[i];
            float l0, l1, l2, l3;
            uint32_t h01 = split_pack_hi(t.x, t.y, l0, l1);
            uint32_t h23 = split_pack_hi(t.z, t.w, l2, l3);
            whi[2 * i]     = h01;
            whi[2 * i + 1] = h23;
            wlo[2 * i]     = pack_bf16(l0, l1);
            wlo[2 * i + 1] = pack_bf16(l2, l3);
        }
    }

    // --- Phase 1: h = concat(l2norm(aggr), x) split to bf16 hi/lo in smem.
    // thread: row r = tid>>1 (0..127), half = tid&1 (32 cols of aggr & x each).
    {
        int r = tid >> 1;
        int half = tid & 1;
        int node = n0 + r;
        float av[32], xv[32];
        if (node < N_NODES) {
            const float4* ar = reinterpret_cast<const float4*>(
                aggr + (size_t)node * D + half * 32);
            const float4* xr = reinterpret_cast<const float4*>(
                xin + (size_t)node * D + half * 32);
#pragma unroll
            for (int i = 0; i < 8; ++i) {
                float4 t = ar[i];
                av[4 * i] = t.x; av[4 * i + 1] = t.y;
                av[4 * i + 2] = t.z; av[4 * i + 3] = t.w;
                float4 u = xr[i];
                xv[4 * i] = u.x; xv[4 * i + 1] = u.y;
                xv[4 * i + 2] = u.z; xv[4 * i + 3] = u.w;
            }
            // zero aggr rows for next layer's aggregation
            float4 z = make_float4(0.f, 0.f, 0.f, 0.f);
            float4* aw = reinterpret_cast<float4*>(aggr + (size_t)node * D + half * 32);
#pragma unroll
            for (int i = 0; i < 8; ++i) aw[i] = z;
        } else {
#pragma unroll
            for (int i = 0; i < 32; ++i) { av[i] = 0.f; xv[i] = 0.f; }
        }
        float ss = 0.f;
#pragma unroll
        for (int i = 0; i < 32; ++i) ss += av[i] * av[i];
        ss += __shfl_xor_sync(0xFFFFFFFFu, ss, 1);
        float inv = 1.0f / fmaxf(sqrtf(ss), 1e-12f);

        uint32_t* hhi = reinterpret_cast<uint32_t*>(smem + SM_HHI + r * (HSTR2 * 2));
        uint32_t* hlo = reinterpret_cast<uint32_t*>(smem + SM_HLO + r * (HSTR2 * 2));
        int c0 = half * 16;           // uint32 index (2 bf16 each)
#pragma unroll
        for (int i = 0; i < 16; ++i) {
            float f0 = av[2 * i] * inv, f1 = av[2 * i + 1] * inv;
            float l0, l1;
            uint32_t h = split_pack_hi(f0, f1, l0, l1);
            hhi[c0 + i] = h;
            hlo[c0 + i] = pack_bf16(l0, l1);
        }
#pragma unroll
        for (int i = 0; i < 16; ++i) {
            float l0, l1;
            uint32_t h = split_pack_hi(xv[2 * i], xv[2 * i + 1], l0, l1);
            hhi[32 + c0 + i] = h;
            hlo[32 + c0 + i] = pack_bf16(l0, l1);
        }
    }
    __syncthreads();

    // --- Phase 2: MMA. warp wid (0..7) owns rows [16*wid, +16), cols 0..63.
    float acc[8][4];
#pragma unroll
    for (int j = 0; j < 8; ++j)
#pragma unroll
        for (int q = 0; q < 4; ++q) acc[j][q] = 0.f;

    {
        int lane15 = lane & 15;
        int laneHi = (lane >> 4) & 1;
        uint32_t a_hi = sbase + SM_HHI + (wid * 16 + lane15) * (HSTR2 * 2) + laneHi * 16;
        uint32_t a_lo = sbase + SM_HLO + (wid * 16 + lane15) * (HSTR2 * 2) + laneHi * 16;
        uint32_t b_hi = sbase + SM_WHI + lane15 * (WSTR2 * 2) + laneHi * 16;
        uint32_t b_lo = sbase + SM_WLO + lane15 * (WSTR2 * 2) + laneHi * 16;

#pragma unroll 2
        for (int ks = 0; ks < 8; ++ks) {
            uint32_t ah0, ah1, ah2, ah3, al0, al1, al2, al3;
            ldsm_x4(a_hi + ks * 32, ah0, ah1, ah2, ah3);
            ldsm_x4(a_lo + ks * 32, al0, al1, al2, al3);
            uint32_t bk = ks * 16 * (WSTR2 * 2);
#pragma unroll
            for (int ch = 0; ch < 4; ++ch) {
                uint32_t bh0, bh1, bh2, bh3, bl0, bl1, bl2, bl3;
                ldsm_x4t(b_hi + bk + ch * 32, bh0, bh1, bh2, bh3);
                ldsm_x4t(b_lo + bk + ch * 32, bl0, bl1, bl2, bl3);
                mma_bf16(acc[2 * ch],     ah0, ah1, ah2, ah3, bh0, bh1);
                mma_bf16(acc[2 * ch],     ah0, ah1, ah2, ah3, bl0, bl1);
                mma_bf16(acc[2 * ch],     al0, al1, al2, al3, bh0, bh1);
                mma_bf16(acc[2 * ch + 1], ah0, ah1, ah2, ah3, bh2, bh3);
                mma_bf16(acc[2 * ch + 1], ah0, ah1, ah2, ah3, bl2, bl3);
                mma_bf16(acc[2 * ch + 1], al0, al1, al2, al3, bh2, bh3);
            }
        }
    }

    // --- Phase 3: bias + per-row l2norm + store.
    {
        const float* bias_s = reinterpret_cast<const float*>(smem + SM_BIAS);
        float ss1 = 0.f, ss2 = 0.f;
#pragma unroll
        for (int j = 0; j < 8; ++j) {
            float2 bb = *reinterpret_cast<const float2*>(bias_s + 8 * j + (lane & 3) * 2);
            acc[j][0] += bb.x; acc[j][1] += bb.y;
            acc[j][2] += bb.x; acc[j][3] += bb.y;
            ss1 += acc[j][0] * acc[j][0] + acc[j][1] * acc[j][1];
            ss2 += acc[j][2] * acc[j][2] + acc[j][3] * acc[j][3];
        }
        ss1 += __shfl_xor_sync(0xFFFFFFFFu, ss1, 1);
        ss1 += __shfl_xor_sync(0xFFFFFFFFu, ss1, 2);
        ss2 += __shfl_xor_sync(0xFFFFFFFFu, ss2, 1);
        ss2 += __shfl_xor_sync(0xFFFFFFFFu, ss2, 2);
        float inv1 = 1.0f / fmaxf(sqrtf(ss1), 1e-12f);
        float inv2 = 1.0f / fmaxf(sqrtf(ss2), 1e-12f);

        int r1 = n0 + wid * 16 + (lane >> 2);
        int r2 = r1 + 8;
        int coff = (lane & 3) * 2;
        if (r1 < N_NODES) {
            float* o = xout + (size_t)r1 * D + coff;
#pragma unroll
            for (int j = 0; j < 8; ++j) {
                float2 t; t.x = acc[j][0] * inv1; t.y = acc[j][1] * inv1;
                *reinterpret_cast<float2*>(o + 8 * j) = t;
            }
        }
        if (r2 < N_NODES) {
            float* o = xout + (size_t)r2 * D + coff;
#pragma unroll
            for (int j = 0; j < 8; ++j) {
                float2 t; t.x = acc[j][2] * inv2; t.y = acc[j][3] * inv2;
                *reinterpret_cast<float2*>(o + 8 * j) = t;
            }
        }
    }
}

// ---------------------------------------------------------------------------
extern "C" void kernel_launch(void* const* d_in, const int* in_sizes, int n_in,
                              void* d_out, int out_size) {
    const float* x  = (const float*)d_in[0];
    const int* ei   = (const int*)d_in[1];
    const float* ew = (const float*)d_in[2];
    const float* W  = (const float*)d_in[3];
    const float* b  = (const float*)d_in[4];
    float* out      = (float*)d_out;

    float *aggr, *buf0, *buf1;
    int* deg;
    cudaGetSymbolAddress((void**)&aggr, g_aggr);
    cudaGetSymbolAddress((void**)&buf0, g_buf0);
    cudaGetSymbolAddress((void**)&buf1, g_buf1);
    cudaGetSymbolAddress((void**)&deg, g_deg);

    cudaFuncSetAttribute(update_kernel,
                         cudaFuncAttributeMaxDynamicSharedMemorySize,
                         SM_TOTAL);

    const int edge_blocks = (N_EDGES + 255) / 256;
    const int agg_blocks = (N_SPANS + 7) / 8;   // 1563

    // CSR build (once per call)
    cudaMemsetAsync(deg, 0, N_NODES * sizeof(int), 0);
    hist_kernel<<<edge_blocks, 256>>>(ei);
    scan_kernel<<<1, SCAN_T>>>();
    permute_kernel<<<edge_blocks, 256>>>(ei, ew);

    // aggr starts zero; update re-zeros it each layer
    cudaMemsetAsync(aggr, 0, (size_t)N_NODES * D * sizeof(float), 0);

    const float* cur = x;
    for (int l = 0; l < N_LAYERS; ++l) {
        aggregate_kernel<<<agg_blocks, 256>>>(cur, aggr);
        float* nxt = (l == N_LAYERS - 1) ? out : ((l & 1) ? buf1 : buf0);
        update_kernel<<<UN_TILES, 256, SM_TOTAL>>>(
            aggr, cur, W + (size_t)l * 2 * D * D, b + (size_t)l * D, nxt);
        cur = nxt;
    }
}

// round 16
// speedup vs baseline: 1.7788x; 1.0428x over previous
#include <cuda_runtime.h>
#include <cuda_bf16.h>
#include <stdint.h>

#define N_NODES 50000
#define N_EDGES 800000
#define D 64
#define N_LAYERS 12

typedef unsigned long long u64;

__device__ float g_aggr[N_NODES * D];
__device__ float g_buf0[N_NODES * D];
__device__ float g_buf1[N_NODES * D];
// CSR-sorted edge arrays (built once per launch)
__device__ int   g_deg[N_NODES];
__device__ int   g_cur[N_NODES];
__device__ int   g_sd[N_EDGES];    // packed: src | (dst << 16)
__device__ float g_w[N_EDGES];
// Pre-split W: [layer][row 0..127][32 x uint32 (bf16x2)], hi and lo parts
__device__ uint32_t g_whi[N_LAYERS * 128 * 32];
__device__ uint32_t g_wlo[N_LAYERS * 128 * 32];

// ===========================================================================
// CSR build: histogram -> scan -> permute (sort edges by dst, pack src|dst)
// ===========================================================================
__global__ void hist_kernel(const int* __restrict__ ei) {
    int e = blockIdx.x * blockDim.x + threadIdx.x;
    if (e < N_EDGES) atomicAdd(&g_deg[ei[N_EDGES + e]], 1);
}

#define SCAN_T 1024
#define SCAN_C 49
__global__ void scan_kernel() {
    __shared__ int part[SCAN_T];
    int t = threadIdx.x;
    int base = t * SCAN_C;
    int s = 0;
    for (int j = 0; j < SCAN_C; ++j) {
        int idx = base + j;
        if (idx < N_NODES) s += g_deg[idx];
    }
    part[t] = s;
    __syncthreads();
    for (int off = 1; off < SCAN_T; off <<= 1) {
        int v = (t >= off) ? part[t - off] : 0;
        __syncthreads();
        part[t] += v;
        __syncthreads();
    }
    int run = (t > 0) ? part[t - 1] : 0;
    for (int j = 0; j < SCAN_C; ++j) {
        int idx = base + j;
        if (idx < N_NODES) {
            g_cur[idx] = run;
            run += g_deg[idx];
        }
    }
}

__global__ void permute_kernel(const int* __restrict__ ei,
                               const float* __restrict__ ew) {
    int e = blockIdx.x * blockDim.x + threadIdx.x;
    if (e >= N_EDGES) return;
    int d = ei[N_EDGES + e];
    int pos = atomicAdd(&g_cur[d], 1);
    g_sd[pos] = ei[e] | (d << 16);
    g_w[pos] = ew[e];
}

// ===========================================================================
// W pre-split: all 12 layers' W -> bf16 (hi, lo) packed pairs. Once per call.
// ===========================================================================
__device__ __forceinline__ uint32_t split_pack_hi(float f0, float f1,
                                                  float& r0, float& r1) {
    __nv_bfloat16 h0 = __float2bfloat16(f0);
    __nv_bfloat16 h1 = __float2bfloat16(f1);
    r0 = f0 - __bfloat162float(h0);
    r1 = f1 - __bfloat162float(h1);
    return ((uint32_t)__bfloat16_as_ushort(h1) << 16) | (uint32_t)__bfloat16_as_ushort(h0);
}
__device__ __forceinline__ uint32_t pack_bf16(float f0, float f1) {
    __nv_bfloat16 h0 = __float2bfloat16(f0);
    __nv_bfloat16 h1 = __float2bfloat16(f1);
    return ((uint32_t)__bfloat16_as_ushort(h1) << 16) | (uint32_t)__bfloat16_as_ushort(h0);
}

#define WSPLIT_N (N_LAYERS * 128 * 32)   // 49152 uint32 pairs
__global__ void split_w_kernel(const float* __restrict__ W) {
    int t = blockIdx.x * blockDim.x + threadIdx.x;
    if (t >= WSPLIT_N) return;
    float2 v = *reinterpret_cast<const float2*>(W + 2 * t);
    float l0, l1;
    uint32_t h = split_pack_hi(v.x, v.y, l0, l1);
    g_whi[t] = h;
    g_wlo[t] = pack_bf16(l0, l1);
}

// ===========================================================================
// Aggregation (R11/R12 winner, unchanged)
// ===========================================================================
#define AGG_SPAN 64
#define N_SPANS (N_EDGES / AGG_SPAN)

__device__ __forceinline__ void flush_v2(float* aggr, int dstn, int lane, float2 a) {
    float* p = aggr + (size_t)dstn * D + 2 * lane;
    u64 gp = (u64)__cvta_generic_to_global(p);
    asm volatile("red.global.add.v2.f32 [%0], {%1,%2};"
                 :: "l"(gp), "f"(a.x), "f"(a.y) : "memory");
}

__global__ void __launch_bounds__(256, 4)
aggregate_kernel(const float* __restrict__ xin, float* __restrict__ aggr) {
    int warp = threadIdx.x >> 5, lane = threadIdx.x & 31;
    int span = blockIdx.x * 8 + warp;
    if (span >= N_SPANS) return;
    int e0 = span * AGG_SPAN;

    const int4* sdp = reinterpret_cast<const int4*>(g_sd + e0);
    const float4* wp = reinterpret_cast<const float4*>(g_w + e0);

    int4 sdA = sdp[0], sdB = sdp[1];
    float4 wA = wp[0], wB = wp[1];

    float2 acc = make_float2(0.f, 0.f);
    int cur = -1;

#pragma unroll
    for (int bt = 0; bt < 8; ++bt) {
        int sd[8] = {sdA.x, sdA.y, sdA.z, sdA.w, sdB.x, sdB.y, sdB.z, sdB.w};
        float wt[8] = {wA.x, wA.y, wA.z, wA.w, wB.x, wB.y, wB.z, wB.w};

        float2 v[8];
#pragma unroll
        for (int j = 0; j < 8; ++j) {
            int src = sd[j] & 0xFFFF;
            v[j] = *reinterpret_cast<const float2*>(xin + (size_t)src * D + 2 * lane);
        }

        if (bt < 7) {
            sdA = sdp[2 * bt + 2];
            sdB = sdp[2 * bt + 3];
            wA = wp[2 * bt + 2];
            wB = wp[2 * bt + 3];
        }

#pragma unroll
        for (int j = 0; j < 8; ++j) {
            int d = ((unsigned)sd[j]) >> 16;
            if (d != cur) {
                if (cur >= 0) flush_v2(aggr, cur, lane, acc);
                acc = make_float2(0.f, 0.f);
                cur = d;
            }
            acc.x += v[j].x * wt[j];
            acc.y += v[j].y * wt[j];
        }
    }
    if (cur >= 0) flush_v2(aggr, cur, lane, acc);
}

// ===========================================================================
// Update via mma.sync m16n8k16 bf16, split precision (hi,lo), fp32 acc.
// 128-node tile, 256 threads / 8 MMA warps, 2 CTA/SM. W pre-split globally.
// ===========================================================================
#define UTB 128
#define UN_TILES ((N_NODES + UTB - 1) / UTB)   // 391

#define HSTR2 136                // bf16 per h row (272 B; 272%128=16 -> ldsm ok)
#define WSTR2 72                 // bf16 per W row (144 B; 144%128=16 -> ldsm ok)
#define SM_BIAS 0
#define SM_HHI  256
#define SM_HLO  (SM_HHI + UTB * HSTR2 * 2)        // +34816
#define SM_WHI  (SM_HLO + UTB * HSTR2 * 2)        // +34816
#define SM_WLO  (SM_WHI + 128 * WSTR2 * 2)        // +18432
#define SM_TOTAL (SM_WLO + 128 * WSTR2 * 2 + 128) // ~107 KB

__device__ __forceinline__ uint32_t smem_u32(const void* p) {
    uint32_t a;
    asm("{ .reg .u64 t; cvta.to.shared.u64 t, %1; cvt.u32.u64 %0, t; }"
        : "=r"(a) : "l"(p));
    return a;
}
__device__ __forceinline__ void ldsm_x4(uint32_t addr, uint32_t& r0, uint32_t& r1,
                                        uint32_t& r2, uint32_t& r3) {
    asm volatile("ldmatrix.sync.aligned.m8n8.x4.shared.b16 {%0,%1,%2,%3}, [%4];"
                 : "=r"(r0), "=r"(r1), "=r"(r2), "=r"(r3) : "r"(addr));
}
__device__ __forceinline__ void ldsm_x4t(uint32_t addr, uint32_t& r0, uint32_t& r1,
                                         uint32_t& r2, uint32_t& r3) {
    asm volatile("ldmatrix.sync.aligned.m8n8.x4.trans.shared.b16 {%0,%1,%2,%3}, [%4];"
                 : "=r"(r0), "=r"(r1), "=r"(r2), "=r"(r3) : "r"(addr));
}
__device__ __forceinline__ void mma_bf16(float* c, uint32_t a0, uint32_t a1,
                                         uint32_t a2, uint32_t a3,
                                         uint32_t b0, uint32_t b1) {
    asm volatile(
        "mma.sync.aligned.m16n8k16.row.col.f32.bf16.bf16.f32 "
        "{%0,%1,%2,%3}, {%4,%5,%6,%7}, {%8,%9}, {%0,%1,%2,%3};"
        : "+f"(c[0]), "+f"(c[1]), "+f"(c[2]), "+f"(c[3])
        : "r"(a0), "r"(a1), "r"(a2), "r"(a3), "r"(b0), "r"(b1));
}

__global__ void __launch_bounds__(256)
update_kernel(float* __restrict__ aggr,
              const float* __restrict__ xin,
              const uint32_t* __restrict__ whi,  // [128][32] layer slice
              const uint32_t* __restrict__ wlo,
              const float* __restrict__ b,       // [64]
              float* __restrict__ xout) {
    extern __shared__ char smem[];
    uint32_t sbase = smem_u32(smem);
    int tid = threadIdx.x;
    int lane = tid & 31;
    int wid = tid >> 5;
    int n0 = blockIdx.x * UTB;

    // --- Stage pre-split W + bias into smem (pure copies, no CVT).
    // Thread: row wr = tid>>1, half wh = tid&1 -> 16 uint32 = 4 uint4.
    {
        float* bias_s = reinterpret_cast<float*>(smem + SM_BIAS);
        if (tid < 64) bias_s[tid] = b[tid];
        int wr = tid >> 1;
        int wh = tid & 1;
        const uint4* ghi = reinterpret_cast<const uint4*>(whi + wr * 32 + wh * 16);
        const uint4* glo = reinterpret_cast<const uint4*>(wlo + wr * 32 + wh * 16);
        uint4* shi = reinterpret_cast<uint4*>(smem + SM_WHI + wr * (WSTR2 * 2) + wh * 64);
        uint4* slo = reinterpret_cast<uint4*>(smem + SM_WLO + wr * (WSTR2 * 2) + wh * 64);
#pragma unroll
        for (int i = 0; i < 4; ++i) {
            shi[i] = ghi[i];
            slo[i] = glo[i];
        }
    }

    // --- Phase 1: h = concat(l2norm(aggr), x) split to bf16 hi/lo in smem.
    // thread: row r = tid>>1 (0..127), half = tid&1 (32 cols of aggr & x each).
    {
        int r = tid >> 1;
        int half = tid & 1;
        int node = n0 + r;
        float av[32], xv[32];
        if (node < N_NODES) {
            const float4* ar = reinterpret_cast<const float4*>(
                aggr + (size_t)node * D + half * 32);
            const float4* xr = reinterpret_cast<const float4*>(
                xin + (size_t)node * D + half * 32);
#pragma unroll
            for (int i = 0; i < 8; ++i) {
                float4 t = ar[i];
                av[4 * i] = t.x; av[4 * i + 1] = t.y;
                av[4 * i + 2] = t.z; av[4 * i + 3] = t.w;
                float4 u = xr[i];
                xv[4 * i] = u.x; xv[4 * i + 1] = u.y;
                xv[4 * i + 2] = u.z; xv[4 * i + 3] = u.w;
            }
            // zero aggr rows for next layer's aggregation
            float4 z = make_float4(0.f, 0.f, 0.f, 0.f);
            float4* aw = reinterpret_cast<float4*>(aggr + (size_t)node * D + half * 32);
#pragma unroll
            for (int i = 0; i < 8; ++i) aw[i] = z;
        } else {
#pragma unroll
            for (int i = 0; i < 32; ++i) { av[i] = 0.f; xv[i] = 0.f; }
        }
        float ss = 0.f;
#pragma unroll
        for (int i = 0; i < 32; ++i) ss += av[i] * av[i];
        ss += __shfl_xor_sync(0xFFFFFFFFu, ss, 1);
        float inv = 1.0f / fmaxf(sqrtf(ss), 1e-12f);

        uint32_t* hhi = reinterpret_cast<uint32_t*>(smem + SM_HHI + r * (HSTR2 * 2));
        uint32_t* hlo = reinterpret_cast<uint32_t*>(smem + SM_HLO + r * (HSTR2 * 2));
        int c0 = half * 16;           // uint32 index (2 bf16 each)
#pragma unroll
        for (int i = 0; i < 16; ++i) {
            float f0 = av[2 * i] * inv, f1 = av[2 * i + 1] * inv;
            float l0, l1;
            uint32_t h = split_pack_hi(f0, f1, l0, l1);
            hhi[c0 + i] = h;
            hlo[c0 + i] = pack_bf16(l0, l1);
        }
#pragma unroll
        for (int i = 0; i < 16; ++i) {
            float l0, l1;
            uint32_t h = split_pack_hi(xv[2 * i], xv[2 * i + 1], l0, l1);
            hhi[32 + c0 + i] = h;
            hlo[32 + c0 + i] = pack_bf16(l0, l1);
        }
    }
    __syncthreads();

    // --- Phase 2: MMA. warp wid (0..7) owns rows [16*wid, +16), cols 0..63.
    float acc[8][4];
#pragma unroll
    for (int j = 0; j < 8; ++j)
#pragma unroll
        for (int q = 0; q < 4; ++q) acc[j][q] = 0.f;

    {
        int lane15 = lane & 15;
        int laneHi = (lane >> 4) & 1;
        uint32_t a_hi = sbase + SM_HHI + (wid * 16 + lane15) * (HSTR2 * 2) + laneHi * 16;
        uint32_t a_lo = sbase + SM_HLO + (wid * 16 + lane15) * (HSTR2 * 2) + laneHi * 16;
        uint32_t b_hi = sbase + SM_WHI + lane15 * (WSTR2 * 2) + laneHi * 16;
        uint32_t b_lo = sbase + SM_WLO + lane15 * (WSTR2 * 2) + laneHi * 16;

#pragma unroll 2
        for (int ks = 0; ks < 8; ++ks) {
            uint32_t ah0, ah1, ah2, ah3, al0, al1, al2, al3;
            ldsm_x4(a_hi + ks * 32, ah0, ah1, ah2, ah3);
            ldsm_x4(a_lo + ks * 32, al0, al1, al2, al3);
            uint32_t bk = ks * 16 * (WSTR2 * 2);
#pragma unroll
            for (int ch = 0; ch < 4; ++ch) {
                uint32_t bh0, bh1, bh2, bh3, bl0, bl1, bl2, bl3;
                ldsm_x4t(b_hi + bk + ch * 32, bh0, bh1, bh2, bh3);
                ldsm_x4t(b_lo + bk + ch * 32, bl0, bl1, bl2, bl3);
                mma_bf16(acc[2 * ch],     ah0, ah1, ah2, ah3, bh0, bh1);
                mma_bf16(acc[2 * ch],     ah0, ah1, ah2, ah3, bl0, bl1);
                mma_bf16(acc[2 * ch],     al0, al1, al2, al3, bh0, bh1);
                mma_bf16(acc[2 * ch + 1], ah0, ah1, ah2, ah3, bh2, bh3);
                mma_bf16(acc[2 * ch + 1], ah0, ah1, ah2, ah3, bl2, bl3);
                mma_bf16(acc[2 * ch + 1], al0, al1, al2, al3, bh2, bh3);
            }
        }
    }

    // --- Phase 3: bias + per-row l2norm + store.
    {
        const float* bias_s = reinterpret_cast<const float*>(smem + SM_BIAS);
        float ss1 = 0.f, ss2 = 0.f;
#pragma unroll
        for (int j = 0; j < 8; ++j) {
            float2 bb = *reinterpret_cast<const float2*>(bias_s + 8 * j + (lane & 3) * 2);
            acc[j][0] += bb.x; acc[j][1] += bb.y;
            acc[j][2] += bb.x; acc[j][3] += bb.y;
            ss1 += acc[j][0] * acc[j][0] + acc[j][1] * acc[j][1];
            ss2 += acc[j][2] * acc[j][2] + acc[j][3] * acc[j][3];
        }
        ss1 += __shfl_xor_sync(0xFFFFFFFFu, ss1, 1);
        ss1 += __shfl_xor_sync(0xFFFFFFFFu, ss1, 2);
        ss2 += __shfl_xor_sync(0xFFFFFFFFu, ss2, 1);
        ss2 += __shfl_xor_sync(0xFFFFFFFFu, ss2, 2);
        float inv1 = 1.0f / fmaxf(sqrtf(ss1), 1e-12f);
        float inv2 = 1.0f / fmaxf(sqrtf(ss2), 1e-12f);

        int r1 = n0 + wid * 16 + (lane >> 2);
        int r2 = r1 + 8;
        int coff = (lane & 3) * 2;
        if (r1 < N_NODES) {
            float* o = xout + (size_t)r1 * D + coff;
#pragma unroll
            for (int j = 0; j < 8; ++j) {
                float2 t; t.x = acc[j][0] * inv1; t.y = acc[j][1] * inv1;
                *reinterpret_cast<float2*>(o + 8 * j) = t;
            }
        }
        if (r2 < N_NODES) {
            float* o = xout + (size_t)r2 * D + coff;
#pragma unroll
            for (int j = 0; j < 8; ++j) {
                float2 t; t.x = acc[j][2] * inv2; t.y = acc[j][3] * inv2;
                *reinterpret_cast<float2*>(o + 8 * j) = t;
            }
        }
    }
}

// ---------------------------------------------------------------------------
extern "C" void kernel_launch(void* const* d_in, const int* in_sizes, int n_in,
                              void* d_out, int out_size) {
    const float* x  = (const float*)d_in[0];
    const int* ei   = (const int*)d_in[1];
    const float* ew = (const float*)d_in[2];
    const float* W  = (const float*)d_in[3];
    const float* b  = (const float*)d_in[4];
    float* out      = (float*)d_out;

    float *aggr, *buf0, *buf1;
    int* deg;
    uint32_t *whi, *wlo;
    cudaGetSymbolAddress((void**)&aggr, g_aggr);
    cudaGetSymbolAddress((void**)&buf0, g_buf0);
    cudaGetSymbolAddress((void**)&buf1, g_buf1);
    cudaGetSymbolAddress((void**)&deg, g_deg);
    cudaGetSymbolAddress((void**)&whi, g_whi);
    cudaGetSymbolAddress((void**)&wlo, g_wlo);

    cudaFuncSetAttribute(update_kernel,
                         cudaFuncAttributeMaxDynamicSharedMemorySize,
                         SM_TOTAL);

    const int edge_blocks = (N_EDGES + 255) / 256;
    const int agg_blocks = (N_SPANS + 7) / 8;   // 1563

    // CSR build + W pre-split (once per call)
    cudaMemsetAsync(deg, 0, N_NODES * sizeof(int), 0);
    hist_kernel<<<edge_blocks, 256>>>(ei);
    scan_kernel<<<1, SCAN_T>>>();
    permute_kernel<<<edge_blocks, 256>>>(ei, ew);
    split_w_kernel<<<(WSPLIT_N + 255) / 256, 256>>>(W);

    // aggr starts zero; update re-zeros it each layer
    cudaMemsetAsync(aggr, 0, (size_t)N_NODES * D * sizeof(float), 0);

    const float* cur = x;
    for (int l = 0; l < N_LAYERS; ++l) {
        aggregate_kernel<<<agg_blocks, 256>>>(cur, aggr);
        float* nxt = (l == N_LAYERS - 1) ? out : ((l & 1) ? buf1 : buf0);
        update_kernel<<<UN_TILES, 256, SM_TOTAL>>>(
            aggr, cur, whi + (size_t)l * 128 * 32, wlo + (size_t)l * 128 * 32,
            b + (size_t)l * D, nxt);
        cur = nxt;
    }
}